// round 13
// baseline (speedup 1.0000x reference)
#include <cuda_runtime.h>
#include <cuda_fp16.h>
#include <math.h>
#include <stdint.h>

// Problem constants (T=4096, NE=DA=2048)
#define TT 4096
#define CC 2048
#define CHUNK 64
#define NCHUNK (TT / CHUNK)

// ---------------- scratch (no cudaMalloc allowed) ----------------
__device__ float g_k[TT * CC];    // exp(k)
__device__ float g_v[TT * CC];    // exp(k)*v
__device__ float g_r[TT * CC];    // sigmoid(r)
// fp16 mixed activations [T, CC] (K-major)
__device__ __half g_ak[TT * CC];
__device__ __half g_av[TT * CC];
__device__ __half g_ar[TT * CC];
// fp16 sr*wkv [T, CC]
__device__ __half g_a2[TT * CC];
// transposed weights [N, K] fp16 (K-major rows)
__device__ __half g_wk[CC * CC];
__device__ __half g_wv[CC * CC];
__device__ __half g_wr[CC * CC];
__device__ __half g_wo[CC * CC];
// scan partials
__device__ float g_pp[NCHUNK * CC];
__device__ float g_pq[NCHUNK * CC];
__device__ float g_ip[NCHUNK * CC];
__device__ float g_iq[NCHUNK * CC];
__device__ float g_ew[CC];
__device__ float g_ewL[CC];
__device__ float g_eu[CC];

// ---------------- per-channel constants ----------------
__global__ void precompute_kernel(const float* __restrict__ tf,
                                  const float* __restrict__ td) {
    int c = blockIdx.x * blockDim.x + threadIdx.x;
    if (c < CC) {
        float w = expf(-expf(td[c]));   // e^w, decay factor per step
        g_ew[c] = w;
        float p = w;
#pragma unroll
        for (int i = 0; i < 6; i++) p = p * p;   // w^64
        g_ewL[c] = p;
        g_eu[c] = expf(tf[c]);
    }
}

// ---------------- weight transpose: W[K,N] -> fp16 [N,K], 4 weights ----------------
__global__ void wsplit4_kernel(const float* __restrict__ W0,
                               const float* __restrict__ W1,
                               const float* __restrict__ W2,
                               const float* __restrict__ W3) {
    __shared__ float tile[32][33];
    const float* W = (blockIdx.z == 0) ? W0 : (blockIdx.z == 1) ? W1
                   : (blockIdx.z == 2) ? W2 : W3;
    __half* H = (blockIdx.z == 0) ? g_wk : (blockIdx.z == 1) ? g_wv
              : (blockIdx.z == 2) ? g_wr : g_wo;
    int n0 = blockIdx.x * 32, k0 = blockIdx.y * 32;
    int tx = threadIdx.x, ty = threadIdx.y;  // 32 x 8
#pragma unroll
    for (int i = 0; i < 32; i += 8)
        tile[ty + i][tx] = W[(long)(k0 + ty + i) * CC + n0 + tx];
    __syncthreads();
#pragma unroll
    for (int i = 0; i < 32; i += 8) {
        float v = tile[tx][ty + i];  // = W[k0+tx][n0+ty+i]
        H[(long)(n0 + ty + i) * CC + k0 + tx] = __float2half_rn(v);
    }
}

// ---------------- activation mix -> fp16 ----------------
__global__ void asplit_kernel(const float* __restrict__ x,
                              const float* __restrict__ tmk,
                              const float* __restrict__ tmv,
                              const float* __restrict__ tmr) {
    int i = blockIdx.x * blockDim.x + threadIdx.x;
    if (i >= TT * CC) return;
    int c = i & (CC - 1);
    float xv = x[i];
    float xx = (i >= CC) ? x[i - CC] : 0.f;
    float d = xv - xx;
    g_ak[i] = __float2half_rn(fmaf(tmk[c], d, xx));
    g_av[i] = __float2half_rn(fmaf(tmv[c], d, xx));
    g_ar[i] = __float2half_rn(fmaf(tmr[c], d, xx));
}

// ---------------- fp16 single-product GEMM via mma.sync ----------------
// C[M,N](fp32) = A[M,K] @ B[N,K]^T, fp16 operands, fp32 accum.
// MODE 0: store acc; 1: store exp(acc); 2: store acc*EK[idx]; 3: store sigmoid(acc)
#define GM 128
#define GN 128
#define GK 64
#define GNS (CC / GK)         // 32 K-stages
#define TILE_BYTES 16384      // 128 rows x 128B (fp16 x 64)
#define BUF_BYTES (2 * TILE_BYTES)
#define NBUF 4
#define SMEM_DYN (NBUF * BUF_BYTES + 1024)

__device__ __forceinline__ uint32_t smem_u32(const void* p) {
    uint32_t a;
    asm("{ .reg .u64 t; cvta.to.shared.u64 t, %1; cvt.u32.u64 %0, t; }"
        : "=r"(a) : "l"(p));
    return a;
}
__device__ __forceinline__ void cp16(uint32_t dst, const void* src) {
    asm volatile("cp.async.cg.shared.global [%0], [%1], 16;" :: "r"(dst), "l"(src) : "memory");
}
__device__ __forceinline__ void ldsm4(uint32_t& r0, uint32_t& r1, uint32_t& r2,
                                      uint32_t& r3, uint32_t addr) {
    asm volatile("ldmatrix.sync.aligned.m8n8.x4.shared.b16 {%0,%1,%2,%3}, [%4];"
                 : "=r"(r0), "=r"(r1), "=r"(r2), "=r"(r3) : "r"(addr));
}
__device__ __forceinline__ void mma16816(float* c, const uint32_t* a,
                                         uint32_t b0, uint32_t b1) {
    asm volatile(
        "mma.sync.aligned.m16n8k16.row.col.f32.f16.f16.f32 "
        "{%0,%1,%2,%3}, {%4,%5,%6,%7}, {%8,%9}, {%0,%1,%2,%3};"
        : "+f"(c[0]), "+f"(c[1]), "+f"(c[2]), "+f"(c[3])
        : "r"(a[0]), "r"(a[1]), "r"(a[2]), "r"(a[3]), "r"(b0), "r"(b1));
}

__device__ __forceinline__ void load_stage(
    uint32_t sb, const __half* A, const __half* B,
    int m0, int n0, int s, int tid) {
    uint32_t base = sb + (uint32_t)(s & (NBUF - 1)) * BUF_BYTES;
    int k0 = s * GK;
#pragma unroll
    for (int i = 0; i < 4; i++) {
        int c = tid + i * 256;          // 0..1023 chunk id
        int row = c >> 3;
        int colb = (c & 7) * 16;        // byte offset within 128B row
        uint32_t off = (uint32_t)(row * 128 + colb);
        uint32_t sw = off ^ ((off >> 3) & 0x70);
        const char* pa = (const char*)(A + (long)(m0 + row) * CC + k0) + colb;
        const char* pb = (const char*)(B + (long)(n0 + row) * CC + k0) + colb;
        cp16(base + sw, pa);
        cp16(base + TILE_BYTES + sw, pb);
    }
    asm volatile("cp.async.commit_group;" ::: "memory");
}

// load one kk-step's ldmatrix operands into registers
__device__ __forceinline__ void load_ops(
    uint32_t ab, uint32_t kb,
    uint32_t aRaw, uint32_t aMsk, uint32_t bRaw, uint32_t bMsk,
    uint32_t ah[4][4], uint32_t bh[4][2]) {
#pragma unroll
    for (int mi = 0; mi < 4; mi++) {
        uint32_t raw = aRaw + (uint32_t)(mi * 2048) + kb;
        ldsm4(ah[mi][0], ah[mi][1], ah[mi][2], ah[mi][3], ab + (raw ^ aMsk));
    }
#pragma unroll
    for (int np = 0; np < 2; np++) {  // each x4 covers two n8 tiles
        uint32_t raw = bRaw + (uint32_t)(np * 2048) + kb;
        ldsm4(bh[np * 2][0], bh[np * 2][1], bh[np * 2 + 1][0],
              bh[np * 2 + 1][1], ab + TILE_BYTES + (raw ^ bMsk));
    }
}

template <int MODE>
__global__ __launch_bounds__(256, 1) void tc_gemm_kernel(
    const __half* __restrict__ A, const __half* __restrict__ B,
    float* __restrict__ C, const float* __restrict__ EK) {
    extern __shared__ char dsm[];
    const int tid = threadIdx.x;
    const int wid = tid >> 5;
    const int lane = tid & 31;
    const int wm = wid & 1;        // 2 warp rows  (64 M each)
    const int wn = wid >> 1;       // 4 warp cols  (32 N each)
    const int m0 = blockIdx.y * GM;
    const int n0 = blockIdx.x * GN;

    uint32_t sb = (smem_u32(dsm) + 1023) & ~1023u;  // 1024-aligned tile base

    // per-thread ldmatrix raw offsets + swizzle masks
    const uint32_t aRow = (uint32_t)(wm * 64 + (lane & 15));
    const uint32_t aRaw = aRow * 128 + (uint32_t)(lane >> 4) * 16;
    const uint32_t aMsk = (aRow & 7) << 4;
    const uint32_t bRow = (uint32_t)(wn * 32 + ((lane >> 4) << 3) + (lane & 7));
    const uint32_t bRaw = bRow * 128 + (uint32_t)((lane >> 3) & 1) * 16;
    const uint32_t bMsk = (bRow & 7) << 4;

    float acc[4][4][4];
#pragma unroll
    for (int mi = 0; mi < 4; mi++)
#pragma unroll
        for (int ni = 0; ni < 4; ni++)
#pragma unroll
            for (int j = 0; j < 4; j++) acc[mi][ni][j] = 0.f;

    load_stage(sb, A, B, m0, n0, 0, tid);
    load_stage(sb, A, B, m0, n0, 1, tid);
    load_stage(sb, A, B, m0, n0, 2, tid);

    for (int s = 0; s < GNS; s++) {
        const uint32_t ab = sb + (uint32_t)(s & (NBUF - 1)) * BUF_BYTES;
        if (s < GNS - 2)       asm volatile("cp.async.wait_group 2;" ::: "memory");
        else if (s == GNS - 2) asm volatile("cp.async.wait_group 1;" ::: "memory");
        else                   asm volatile("cp.async.wait_group 0;" ::: "memory");
        __syncthreads();

        // issue next stage's global loads FIRST so they overlap the MMAs.
        // buffer (s+3)&3 == (s-1)&3 was fully consumed before this sync.
        if (s + 3 < GNS)
            load_stage(sb, A, B, m0, n0, s + 3, tid);

        // register-pipelined mainloop over 4 kk-steps
        uint32_t ah[2][4][4], bh[2][4][2];
        load_ops(ab, 0, aRaw, aMsk, bRaw, bMsk, ah[0], bh[0]);
#pragma unroll
        for (int kk = 0; kk < 4; kk++) {
            if (kk < 3)
                load_ops(ab, (uint32_t)((kk + 1) * 32), aRaw, aMsk, bRaw, bMsk,
                         ah[(kk + 1) & 1], bh[(kk + 1) & 1]);
#pragma unroll
            for (int mi = 0; mi < 4; mi++)
#pragma unroll
                for (int ni = 0; ni < 4; ni++)
                    mma16816(acc[mi][ni], ah[kk & 1][mi],
                             bh[kk & 1][ni][0], bh[kk & 1][ni][1]);
        }
    }

    // epilogue: transform + write fp32
    const int rq = lane >> 2;
    const int cq = (lane & 3) * 2;
#pragma unroll
    for (int mi = 0; mi < 4; mi++) {
        int mrow = m0 + wm * 64 + mi * 16 + rq;
#pragma unroll
        for (int ni = 0; ni < 4; ni++) {
            long o0 = (long)mrow * CC + n0 + wn * 32 + ni * 8 + cq;
            long o1 = o0 + 8L * CC;
            float2 r0 = make_float2(acc[mi][ni][0], acc[mi][ni][1]);
            float2 r1 = make_float2(acc[mi][ni][2], acc[mi][ni][3]);
            if (MODE == 1) {           // exp(k)
                r0.x = expf(r0.x); r0.y = expf(r0.y);
                r1.x = expf(r1.x); r1.y = expf(r1.y);
            } else if (MODE == 2) {    // exp(k)*v
                float2 e0 = *reinterpret_cast<const float2*>(EK + o0);
                float2 e1 = *reinterpret_cast<const float2*>(EK + o1);
                r0.x *= e0.x; r0.y *= e0.y;
                r1.x *= e1.x; r1.y *= e1.y;
            } else if (MODE == 3) {    // sigmoid(r)
                r0.x = 1.f / (1.f + expf(-r0.x));
                r0.y = 1.f / (1.f + expf(-r0.y));
                r1.x = 1.f / (1.f + expf(-r1.x));
                r1.y = 1.f / (1.f + expf(-r1.y));
            }
            *reinterpret_cast<float2*>(C + o0) = r0;
            *reinterpret_cast<float2*>(C + o1) = r1;
        }
    }
}

// ---------------- chunked linear-recurrence scan ----------------
// g_k holds ek=exp(k), g_v holds ekv=exp(k)*v, g_r holds sr=sigmoid(r).
__global__ void scan1_kernel() {
    int c = blockIdx.y * blockDim.x + threadIdx.x;
    int ch = blockIdx.x;
    float w = g_ew[c];
    float P = 0.f, Q = 0.f;
    int idx = ch * CHUNK * CC + c;
#pragma unroll 8
    for (int i = 0; i < CHUNK; i++) {
        P = fmaf(w, P, g_v[idx]);
        Q = fmaf(w, Q, g_k[idx]);
        idx += CC;
    }
    g_pp[ch * CC + c] = P;
    g_pq[ch * CC + c] = Q;
}

__global__ void scan2_kernel() {
    int c = blockIdx.x * blockDim.x + threadIdx.x;
    float wl = g_ewL[c];
    float P = 0.f, Q = 0.f;
#pragma unroll
    for (int j = 0; j < NCHUNK; j++) {
        g_ip[j * CC + c] = P;
        g_iq[j * CC + c] = Q;
        P = fmaf(wl, P, g_pp[j * CC + c]);
        Q = fmaf(wl, Q, g_pq[j * CC + c]);
    }
}

__global__ void scan3_kernel() {
    int c = blockIdx.y * blockDim.x + threadIdx.x;
    int ch = blockIdx.x;
    float w = g_ew[c], eu = g_eu[c];
    float P = g_ip[ch * CC + c], Q = g_iq[ch * CC + c];
    int idx = ch * CHUNK * CC + c;
#pragma unroll 4
    for (int i = 0; i < CHUNK; i++) {
        float ek = g_k[idx];
        float ekv = g_v[idx];
        float num = fmaf(eu, ekv, P);
        float den = fmaf(eu, ek, Q);
        float y = g_r[idx] * __fdividef(num, den);
        g_a2[idx] = __float2half_rn(y);
        P = fmaf(w, P, ekv);
        Q = fmaf(w, Q, ek);
        idx += CC;
    }
}

// ---------------- launch ----------------
extern "C" void kernel_launch(void* const* d_in, const int* in_sizes, int n_in,
                              void* d_out, int out_size) {
    const float* x   = (const float*)d_in[0];
    const float* tf  = (const float*)d_in[1];
    const float* td  = (const float*)d_in[2];
    const float* tmk = (const float*)d_in[3];
    const float* tmv = (const float*)d_in[4];
    const float* tmr = (const float*)d_in[5];
    const float* Wk  = (const float*)d_in[6];
    const float* Wv  = (const float*)d_in[7];
    const float* Wr  = (const float*)d_in[8];
    const float* Wo  = (const float*)d_in[9];
    float* out = (float*)d_out;

    float *pk, *pv, *pr;
    cudaGetSymbolAddress((void**)&pk, g_k);
    cudaGetSymbolAddress((void**)&pv, g_v);
    cudaGetSymbolAddress((void**)&pr, g_r);
    __half *ak, *av, *ar, *a2, *wk, *wv, *wr, *wo;
    cudaGetSymbolAddress((void**)&ak, g_ak);
    cudaGetSymbolAddress((void**)&av, g_av);
    cudaGetSymbolAddress((void**)&ar, g_ar);
    cudaGetSymbolAddress((void**)&a2, g_a2);
    cudaGetSymbolAddress((void**)&wk, g_wk);
    cudaGetSymbolAddress((void**)&wv, g_wv);
    cudaGetSymbolAddress((void**)&wr, g_wr);
    cudaGetSymbolAddress((void**)&wo, g_wo);

    cudaFuncSetAttribute(tc_gemm_kernel<0>,
                         cudaFuncAttributeMaxDynamicSharedMemorySize, SMEM_DYN);
    cudaFuncSetAttribute(tc_gemm_kernel<1>,
                         cudaFuncAttributeMaxDynamicSharedMemorySize, SMEM_DYN);
    cudaFuncSetAttribute(tc_gemm_kernel<2>,
                         cudaFuncAttributeMaxDynamicSharedMemorySize, SMEM_DYN);
    cudaFuncSetAttribute(tc_gemm_kernel<3>,
                         cudaFuncAttributeMaxDynamicSharedMemorySize, SMEM_DYN);

    precompute_kernel<<<(CC + 255) / 256, 256>>>(tf, td);

    wsplit4_kernel<<<dim3(CC / 32, CC / 32, 4), dim3(32, 8)>>>(Wk, Wv, Wr, Wo);

    asplit_kernel<<<(TT * CC + 255) / 256, 256>>>(x, tmk, tmv, tmr);

    dim3 gg(CC / GN, TT / GM);
    tc_gemm_kernel<1><<<gg, 256, SMEM_DYN>>>(ak, wk, pk, nullptr);
    tc_gemm_kernel<2><<<gg, 256, SMEM_DYN>>>(av, wv, pv, pk);
    tc_gemm_kernel<3><<<gg, 256, SMEM_DYN>>>(ar, wr, pr, nullptr);

    scan1_kernel<<<dim3(NCHUNK, CC / 256), 256>>>();
    scan2_kernel<<<CC / 256, 256>>>();
    scan3_kernel<<<dim3(NCHUNK, CC / 256), 256>>>();

    tc_gemm_kernel<0><<<gg, 256, SMEM_DYN>>>(a2, wo, out, nullptr);
}

// round 14
// speedup vs baseline: 1.1440x; 1.1440x over previous
#include <cuda_runtime.h>
#include <cuda_fp16.h>
#include <math.h>
#include <stdint.h>

// Problem constants (T=4096, NE=DA=2048)
#define TT 4096
#define CC 2048
#define CHUNK 64
#define NCHUNK (TT / CHUNK)

// ---------------- scratch (no cudaMalloc allowed) ----------------
__device__ float g_k[TT * CC];    // exp(k)
__device__ float g_v[TT * CC];    // v (raw)
__device__ float g_r[TT * CC];    // sigmoid(r)
// fp16 mixed activations [T, CC] (K-major)
__device__ __half g_ak[TT * CC];
__device__ __half g_av[TT * CC];
__device__ __half g_ar[TT * CC];
// fp16 sr*wkv [T, CC]
__device__ __half g_a2[TT * CC];
// transposed weights [N, K] fp16 (K-major rows)
__device__ __half g_wk[CC * CC];
__device__ __half g_wv[CC * CC];
__device__ __half g_wr[CC * CC];
__device__ __half g_wo[CC * CC];
// scan partials
__device__ float g_pp[NCHUNK * CC];
__device__ float g_pq[NCHUNK * CC];
__device__ float g_ip[NCHUNK * CC];
__device__ float g_iq[NCHUNK * CC];
__device__ float g_ew[CC];
__device__ float g_ewL[CC];
__device__ float g_eu[CC];

// ---------------- per-channel constants ----------------
__global__ void precompute_kernel(const float* __restrict__ tf,
                                  const float* __restrict__ td) {
    int c = blockIdx.x * blockDim.x + threadIdx.x;
    if (c < CC) {
        float w = expf(-expf(td[c]));   // e^w, decay factor per step
        g_ew[c] = w;
        float p = w;
#pragma unroll
        for (int i = 0; i < 6; i++) p = p * p;   // w^64
        g_ewL[c] = p;
        g_eu[c] = expf(tf[c]);
    }
}

// ---------------- weight transpose: W[K,N] -> fp16 [N,K], 4 weights ----------------
__global__ void wsplit4_kernel(const float* __restrict__ W0,
                               const float* __restrict__ W1,
                               const float* __restrict__ W2,
                               const float* __restrict__ W3) {
    __shared__ float tile[32][33];
    const float* W = (blockIdx.z == 0) ? W0 : (blockIdx.z == 1) ? W1
                   : (blockIdx.z == 2) ? W2 : W3;
    __half* H = (blockIdx.z == 0) ? g_wk : (blockIdx.z == 1) ? g_wv
              : (blockIdx.z == 2) ? g_wr : g_wo;
    int n0 = blockIdx.x * 32, k0 = blockIdx.y * 32;
    int tx = threadIdx.x, ty = threadIdx.y;  // 32 x 8
#pragma unroll
    for (int i = 0; i < 32; i += 8)
        tile[ty + i][tx] = W[(long)(k0 + ty + i) * CC + n0 + tx];
    __syncthreads();
#pragma unroll
    for (int i = 0; i < 32; i += 8) {
        float v = tile[tx][ty + i];  // = W[k0+tx][n0+ty+i]
        H[(long)(n0 + ty + i) * CC + k0 + tx] = __float2half_rn(v);
    }
}

// ---------------- activation mix -> fp16 ----------------
__global__ void asplit_kernel(const float* __restrict__ x,
                              const float* __restrict__ tmk,
                              const float* __restrict__ tmv,
                              const float* __restrict__ tmr) {
    int i = blockIdx.x * blockDim.x + threadIdx.x;
    if (i >= TT * CC) return;
    int c = i & (CC - 1);
    float xv = x[i];
    float xx = (i >= CC) ? x[i - CC] : 0.f;
    float d = xv - xx;
    g_ak[i] = __float2half_rn(fmaf(tmk[c], d, xx));
    g_av[i] = __float2half_rn(fmaf(tmv[c], d, xx));
    g_ar[i] = __float2half_rn(fmaf(tmr[c], d, xx));
}

// ---------------- fp16 GEMM via mma.sync, 128x64 tile, 2 CTAs/SM ----------------
// C[M,N](fp32) = A[M,K] @ B[N,K]^T.  mode: 0 none, 1 exp, 2 sigmoid.
#define GM 128
#define GN 64
#define GK 64
#define GNS (CC / GK)         // 32 K-stages
#define A_BYTES 16384         // 128 rows x 128B
#define B_BYTES 8192          // 64 rows x 128B
#define BUF_BYTES (A_BYTES + B_BYTES)   // 24576
#define NBUF 4
#define SMEM_DYN (NBUF * BUF_BYTES + 1024)

__device__ __forceinline__ uint32_t smem_u32(const void* p) {
    uint32_t a;
    asm("{ .reg .u64 t; cvta.to.shared.u64 t, %1; cvt.u32.u64 %0, t; }"
        : "=r"(a) : "l"(p));
    return a;
}
__device__ __forceinline__ void cp16(uint32_t dst, const void* src) {
    asm volatile("cp.async.cg.shared.global [%0], [%1], 16;" :: "r"(dst), "l"(src) : "memory");
}
__device__ __forceinline__ void ldsm4(uint32_t& r0, uint32_t& r1, uint32_t& r2,
                                      uint32_t& r3, uint32_t addr) {
    asm volatile("ldmatrix.sync.aligned.m8n8.x4.shared.b16 {%0,%1,%2,%3}, [%4];"
                 : "=r"(r0), "=r"(r1), "=r"(r2), "=r"(r3) : "r"(addr));
}
__device__ __forceinline__ void mma16816(float* c, const uint32_t* a,
                                         uint32_t b0, uint32_t b1) {
    asm volatile(
        "mma.sync.aligned.m16n8k16.row.col.f32.f16.f16.f32 "
        "{%0,%1,%2,%3}, {%4,%5,%6,%7}, {%8,%9}, {%0,%1,%2,%3};"
        : "+f"(c[0]), "+f"(c[1]), "+f"(c[2]), "+f"(c[3])
        : "r"(a[0]), "r"(a[1]), "r"(a[2]), "r"(a[3]), "r"(b0), "r"(b1));
}

// stage loader: A 128 rows + B 64 rows, 6 x 16B chunks per thread
__device__ __forceinline__ void load_stage(
    uint32_t sb, const __half* A, const __half* B,
    int m0, int n0, int s, int tid) {
    uint32_t base = sb + (uint32_t)(s & (NBUF - 1)) * BUF_BYTES;
    int k0 = s * GK;
#pragma unroll
    for (int i = 0; i < 6; i++) {
        int c = tid + i * 256;          // 0..1535 chunk id
        int colb = (c & 7) * 16;        // byte offset within 128B row
        uint32_t off;
        const char* src;
        if (c < 1024) {                 // A chunk
            int row = c >> 3;
            off = (uint32_t)(row * 128 + colb);
            src = (const char*)(A + (long)(m0 + row) * CC + k0) + colb;
        } else {                        // B chunk
            int row = (c - 1024) >> 3;
            off = (uint32_t)(A_BYTES + row * 128 + colb);
            src = (const char*)(B + (long)(n0 + row) * CC + k0) + colb;
        }
        uint32_t sw = off ^ ((off >> 3) & 0x70);
        cp16(base + sw, src);
    }
    asm volatile("cp.async.commit_group;" ::: "memory");
}

// core mainloop + epilogue, shared by both GEMM kernels
__device__ __forceinline__ void gemm_core(
    const __half* __restrict__ A, const __half* __restrict__ B,
    float* __restrict__ C, int mode, int m0, int n0, char* dsm) {
    const int tid = threadIdx.x;
    const int wid = tid >> 5;
    const int lane = tid & 31;
    const int wm = wid & 3;        // 4 warp rows (32 M each)
    const int wn = wid >> 2;       // 2 warp cols (32 N each)

    uint32_t sb = (smem_u32(dsm) + 1023) & ~1023u;

    // ldmatrix base offsets + swizzle masks (constant per thread)
    const uint32_t aRow = (uint32_t)(wm * 32 + (lane & 15));
    const uint32_t aRaw = aRow * 128 + (uint32_t)(lane >> 4) * 16;
    const uint32_t aMsk = (aRow & 7) << 4;
    const uint32_t bRow = (uint32_t)(wn * 32 + ((lane >> 4) << 3) + (lane & 7));
    const uint32_t bRaw = bRow * 128 + (uint32_t)((lane >> 3) & 1) * 16;
    const uint32_t bMsk = (bRow & 7) << 4;

    float acc[2][4][4];
#pragma unroll
    for (int mi = 0; mi < 2; mi++)
#pragma unroll
        for (int ni = 0; ni < 4; ni++)
#pragma unroll
            for (int j = 0; j < 4; j++) acc[mi][ni][j] = 0.f;

    load_stage(sb, A, B, m0, n0, 0, tid);
    load_stage(sb, A, B, m0, n0, 1, tid);
    load_stage(sb, A, B, m0, n0, 2, tid);

    for (int s = 0; s < GNS; s++) {
        const uint32_t ab = sb + (uint32_t)(s & (NBUF - 1)) * BUF_BYTES;
        if (s < GNS - 2)       asm volatile("cp.async.wait_group 2;" ::: "memory");
        else if (s == GNS - 2) asm volatile("cp.async.wait_group 1;" ::: "memory");
        else                   asm volatile("cp.async.wait_group 0;" ::: "memory");
        __syncthreads();

#pragma unroll
        for (int kk = 0; kk < 4; kk++) {
            const uint32_t kb = (uint32_t)(kk * 32);  // 16 fp16 per kstep
            uint32_t ah[2][4], bh[4][2];
#pragma unroll
            for (int mi = 0; mi < 2; mi++) {
                uint32_t raw = aRaw + (uint32_t)(mi * 2048) + kb;
                ldsm4(ah[mi][0], ah[mi][1], ah[mi][2], ah[mi][3],
                      ab + (raw ^ aMsk));
            }
#pragma unroll
            for (int np = 0; np < 2; np++) {  // each x4 covers two n8 tiles
                uint32_t raw = bRaw + (uint32_t)(np * 2048) + kb;
                ldsm4(bh[np * 2][0], bh[np * 2][1], bh[np * 2 + 1][0],
                      bh[np * 2 + 1][1], ab + A_BYTES + (raw ^ bMsk));
            }
#pragma unroll
            for (int mi = 0; mi < 2; mi++)
#pragma unroll
                for (int ni = 0; ni < 4; ni++)
                    mma16816(acc[mi][ni], ah[mi], bh[ni][0], bh[ni][1]);
        }
        if (s + 3 < GNS)
            load_stage(sb, A, B, m0, n0, s + 3, tid);
    }

    // epilogue
    const int rq = lane >> 2;
    const int cq = (lane & 3) * 2;
#pragma unroll
    for (int mi = 0; mi < 2; mi++) {
        int mrow = m0 + wm * 32 + mi * 16 + rq;
#pragma unroll
        for (int ni = 0; ni < 4; ni++) {
            long o0 = (long)mrow * CC + n0 + wn * 32 + ni * 8 + cq;
            long o1 = o0 + 8L * CC;
            float2 r0 = make_float2(acc[mi][ni][0], acc[mi][ni][1]);
            float2 r1 = make_float2(acc[mi][ni][2], acc[mi][ni][3]);
            if (mode == 1) {           // exp
                r0.x = expf(r0.x); r0.y = expf(r0.y);
                r1.x = expf(r1.x); r1.y = expf(r1.y);
            } else if (mode == 2) {    // sigmoid
                r0.x = 1.f / (1.f + expf(-r0.x));
                r0.y = 1.f / (1.f + expf(-r0.y));
                r1.x = 1.f / (1.f + expf(-r1.x));
                r1.y = 1.f / (1.f + expf(-r1.y));
            }
            *reinterpret_cast<float2*>(C + o0) = r0;
            *reinterpret_cast<float2*>(C + o1) = r1;
        }
    }
}

// fused k/v/r GEMM: grid.z selects operand set; 3072 CTAs total
__global__ __launch_bounds__(256, 2) void gemm3_kernel() {
    extern __shared__ char dsm[];
    int z = blockIdx.z;
    const __half* A = (z == 0) ? g_ak : (z == 1) ? g_av : g_ar;
    const __half* B = (z == 0) ? g_wk : (z == 1) ? g_wv : g_wr;
    float* C = (z == 0) ? g_k : (z == 1) ? g_v : g_r;
    int mode = (z == 0) ? 1 : (z == 1) ? 0 : 2;
    gemm_core(A, B, C, mode, blockIdx.y * GM, blockIdx.x * GN, dsm);
}

// output GEMM
__global__ __launch_bounds__(256, 2) void gemmo_kernel(float* __restrict__ C) {
    extern __shared__ char dsm[];
    gemm_core(g_a2, g_wo, C, 0, blockIdx.y * GM, blockIdx.x * GN, dsm);
}

// ---------------- chunked linear-recurrence scan ----------------
// g_k holds ek=exp(k), g_v holds v raw, g_r holds sr=sigmoid(r).
__global__ void scan1_kernel() {
    int c = blockIdx.y * blockDim.x + threadIdx.x;
    int ch = blockIdx.x;
    float w = g_ew[c];
    float P = 0.f, Q = 0.f;
    int idx = ch * CHUNK * CC + c;
#pragma unroll 8
    for (int i = 0; i < CHUNK; i++) {
        float ek = g_k[idx];
        P = fmaf(w, P, ek * g_v[idx]);
        Q = fmaf(w, Q, ek);
        idx += CC;
    }
    g_pp[ch * CC + c] = P;
    g_pq[ch * CC + c] = Q;
}

__global__ void scan2_kernel() {
    int c = blockIdx.x * blockDim.x + threadIdx.x;
    float wl = g_ewL[c];
    float P = 0.f, Q = 0.f;
#pragma unroll
    for (int j = 0; j < NCHUNK; j++) {
        g_ip[j * CC + c] = P;
        g_iq[j * CC + c] = Q;
        P = fmaf(wl, P, g_pp[j * CC + c]);
        Q = fmaf(wl, Q, g_pq[j * CC + c]);
    }
}

__global__ void scan3_kernel() {
    int c = blockIdx.y * blockDim.x + threadIdx.x;
    int ch = blockIdx.x;
    float w = g_ew[c], eu = g_eu[c];
    float P = g_ip[ch * CC + c], Q = g_iq[ch * CC + c];
    int idx = ch * CHUNK * CC + c;
#pragma unroll 4
    for (int i = 0; i < CHUNK; i++) {
        float ek = g_k[idx];
        float ekv = ek * g_v[idx];
        float num = fmaf(eu, ekv, P);
        float den = fmaf(eu, ek, Q);
        float y = g_r[idx] * __fdividef(num, den);
        g_a2[idx] = __float2half_rn(y);
        P = fmaf(w, P, ekv);
        Q = fmaf(w, Q, ek);
        idx += CC;
    }
}

// ---------------- launch ----------------
extern "C" void kernel_launch(void* const* d_in, const int* in_sizes, int n_in,
                              void* d_out, int out_size) {
    const float* x   = (const float*)d_in[0];
    const float* tf  = (const float*)d_in[1];
    const float* td  = (const float*)d_in[2];
    const float* tmk = (const float*)d_in[3];
    const float* tmv = (const float*)d_in[4];
    const float* tmr = (const float*)d_in[5];
    const float* Wk  = (const float*)d_in[6];
    const float* Wv  = (const float*)d_in[7];
    const float* Wr  = (const float*)d_in[8];
    const float* Wo  = (const float*)d_in[9];
    float* out = (float*)d_out;

    cudaFuncSetAttribute(gemm3_kernel,
                         cudaFuncAttributeMaxDynamicSharedMemorySize, SMEM_DYN);
    cudaFuncSetAttribute(gemmo_kernel,
                         cudaFuncAttributeMaxDynamicSharedMemorySize, SMEM_DYN);

    precompute_kernel<<<(CC + 255) / 256, 256>>>(tf, td);

    wsplit4_kernel<<<dim3(CC / 32, CC / 32, 4), dim3(32, 8)>>>(Wk, Wv, Wr, Wo);

    asplit_kernel<<<(TT * CC + 255) / 256, 256>>>(x, tmk, tmv, tmr);

    gemm3_kernel<<<dim3(CC / GN, TT / GM, 3), 256, SMEM_DYN>>>();

    scan1_kernel<<<dim3(NCHUNK, CC / 256), 256>>>();
    scan2_kernel<<<CC / 256, 256>>>();
    scan3_kernel<<<dim3(NCHUNK, CC / 256), 256>>>();

    gemmo_kernel<<<dim3(CC / GN, TT / GM), 256, SMEM_DYN>>>(out);
}

// round 15
// speedup vs baseline: 1.3337x; 1.1658x over previous
#include <cuda_runtime.h>
#include <cuda_fp16.h>
#include <math.h>
#include <stdint.h>

// Problem constants (T=4096, NE=DA=2048)
#define TT 4096
#define CC 2048
#define CHUNK 64
#define NCHUNK (TT / CHUNK)

// ---------------- scratch (no cudaMalloc allowed) ----------------
__device__ float g_k[TT * CC];    // exp(k)
__device__ float g_v[TT * CC];    // v (raw)
__device__ float g_r[TT * CC];    // sigmoid(r)
// fp16 mixed activations [T, CC] (K-major)
__device__ __half g_ak[TT * CC];
__device__ __half g_av[TT * CC];
__device__ __half g_ar[TT * CC];
// fp16 sr*wkv [T, CC]
__device__ __half g_a2[TT * CC];
// transposed weights [N, K] fp16 (K-major rows)
__device__ __half g_wk[CC * CC];
__device__ __half g_wv[CC * CC];
__device__ __half g_wr[CC * CC];
__device__ __half g_wo[CC * CC];
// scan partials
__device__ float g_pp[NCHUNK * CC];
__device__ float g_pq[NCHUNK * CC];
__device__ float g_ip[NCHUNK * CC];
__device__ float g_iq[NCHUNK * CC];
__device__ float g_ew[CC];
__device__ float g_ewL[CC];
__device__ float g_eu[CC];

// ---------------- per-channel constants ----------------
__global__ void precompute_kernel(const float* __restrict__ tf,
                                  const float* __restrict__ td) {
    int c = blockIdx.x * blockDim.x + threadIdx.x;
    if (c < CC) {
        float w = expf(-expf(td[c]));   // e^w, decay factor per step
        g_ew[c] = w;
        float p = w;
#pragma unroll
        for (int i = 0; i < 6; i++) p = p * p;   // w^64
        g_ewL[c] = p;
        g_eu[c] = expf(tf[c]);
    }
}

// ---------------- weight transpose: W[K,N] -> fp16 [N,K], 4 weights ----------------
__global__ void wsplit4_kernel(const float* __restrict__ W0,
                               const float* __restrict__ W1,
                               const float* __restrict__ W2,
                               const float* __restrict__ W3) {
    __shared__ float tile[32][33];
    const float* W = (blockIdx.z == 0) ? W0 : (blockIdx.z == 1) ? W1
                   : (blockIdx.z == 2) ? W2 : W3;
    __half* H = (blockIdx.z == 0) ? g_wk : (blockIdx.z == 1) ? g_wv
              : (blockIdx.z == 2) ? g_wr : g_wo;
    int n0 = blockIdx.x * 32, k0 = blockIdx.y * 32;
    int tx = threadIdx.x, ty = threadIdx.y;  // 32 x 8
#pragma unroll
    for (int i = 0; i < 32; i += 8)
        tile[ty + i][tx] = W[(long)(k0 + ty + i) * CC + n0 + tx];
    __syncthreads();
#pragma unroll
    for (int i = 0; i < 32; i += 8) {
        float v = tile[tx][ty + i];  // = W[k0+tx][n0+ty+i]
        H[(long)(n0 + ty + i) * CC + k0 + tx] = __float2half_rn(v);
    }
}

// ---------------- activation mix -> fp16 ----------------
__global__ void asplit_kernel(const float* __restrict__ x,
                              const float* __restrict__ tmk,
                              const float* __restrict__ tmv,
                              const float* __restrict__ tmr) {
    int i = blockIdx.x * blockDim.x + threadIdx.x;
    if (i >= TT * CC) return;
    int c = i & (CC - 1);
    float xv = x[i];
    float xx = (i >= CC) ? x[i - CC] : 0.f;
    float d = xv - xx;
    g_ak[i] = __float2half_rn(fmaf(tmk[c], d, xx));
    g_av[i] = __float2half_rn(fmaf(tmv[c], d, xx));
    g_ar[i] = __float2half_rn(fmaf(tmr[c], d, xx));
}

// ---------------- fp16 GEMM via mma.sync ----------------
// 128x64 CTA tile, 4 warps (warp tile 64x32), 3 CTAs/SM, NBUF=3.
// C[M,N](fp32) = A[M,K] @ B[N,K]^T.  mode: 0 none, 1 exp, 2 sigmoid.
#define GM 128
#define GN 64
#define GK 64
#define GNS (CC / GK)         // 32 K-stages
#define A_BYTES 16384         // 128 rows x 128B
#define B_BYTES 8192          // 64 rows x 128B
#define BUF_BYTES (A_BYTES + B_BYTES)   // 24576
#define NBUF 3
#define SMEM_DYN (NBUF * BUF_BYTES + 1024)

__device__ __forceinline__ uint32_t smem_u32(const void* p) {
    uint32_t a;
    asm("{ .reg .u64 t; cvta.to.shared.u64 t, %1; cvt.u32.u64 %0, t; }"
        : "=r"(a) : "l"(p));
    return a;
}
__device__ __forceinline__ void cp16(uint32_t dst, const void* src) {
    asm volatile("cp.async.cg.shared.global [%0], [%1], 16;" :: "r"(dst), "l"(src) : "memory");
}
__device__ __forceinline__ void ldsm4(uint32_t& r0, uint32_t& r1, uint32_t& r2,
                                      uint32_t& r3, uint32_t addr) {
    asm volatile("ldmatrix.sync.aligned.m8n8.x4.shared.b16 {%0,%1,%2,%3}, [%4];"
                 : "=r"(r0), "=r"(r1), "=r"(r2), "=r"(r3) : "r"(addr));
}
__device__ __forceinline__ void mma16816(float* c, const uint32_t* a,
                                         uint32_t b0, uint32_t b1) {
    asm volatile(
        "mma.sync.aligned.m16n8k16.row.col.f32.f16.f16.f32 "
        "{%0,%1,%2,%3}, {%4,%5,%6,%7}, {%8,%9}, {%0,%1,%2,%3};"
        : "+f"(c[0]), "+f"(c[1]), "+f"(c[2]), "+f"(c[3])
        : "r"(a[0]), "r"(a[1]), "r"(a[2]), "r"(a[3]), "r"(b0), "r"(b1));
}

// Per-thread stage loader with fully precomputed addresses.
// 128 threads x 12 chunks of 16B = 24KB/stage (A 8 chunks, B 4 chunks).
// For a fixed tid: chunk c = tid + 128*i -> colb = (tid&7)*16 constant,
// row = (tid>>3) + 16*i. Swizzle mask depends only on row.
struct Loader {
    uint32_t swoff[12];   // swizzled smem offset within buffer
    uint32_t goff[12];    // gmem byte offset (stage 0)
};

__device__ __forceinline__ void loader_init(Loader& L, int tid, int m0, int n0) {
    const int r0 = tid >> 3;             // 0..15
    const int colb = (tid & 7) * 16;
#pragma unroll
    for (int i = 0; i < 8; i++) {        // A rows r0 + 16i (0..127)
        int row = r0 + i * 16;
        uint32_t off = (uint32_t)(row * 128 + colb);
        L.swoff[i] = off ^ (uint32_t)((row & 7) << 4);
        L.goff[i] = (uint32_t)((m0 + row) * (CC * 2) + colb);
    }
#pragma unroll
    for (int i = 0; i < 4; i++) {        // B rows r0 + 16i (0..63)
        int row = r0 + i * 16;
        uint32_t off = (uint32_t)(A_BYTES + row * 128 + colb);
        L.swoff[8 + i] = off ^ (uint32_t)((row & 7) << 4);
        L.goff[8 + i] = (uint32_t)((n0 + row) * (CC * 2) + colb);
    }
}

__device__ __forceinline__ void load_stage(const Loader& L, uint32_t sb,
                                           const char* A, const char* B, int s) {
    uint32_t base = sb + (uint32_t)((s % NBUF) * BUF_BYTES);
    uint32_t kadd = (uint32_t)(s * 128);   // 64 fp16 = 128B per stage
#pragma unroll
    for (int i = 0; i < 8; i++)
        cp16(base + L.swoff[i], A + L.goff[i] + kadd);
#pragma unroll
    for (int i = 0; i < 4; i++)
        cp16(base + L.swoff[8 + i], B + L.goff[8 + i] + kadd);
    asm volatile("cp.async.commit_group;" ::: "memory");
}

// core mainloop + epilogue
__device__ __forceinline__ void gemm_core(
    const __half* __restrict__ A, const __half* __restrict__ B,
    float* __restrict__ C, int mode, int m0, int n0, char* dsm) {
    const int tid = threadIdx.x;
    const int wid = tid >> 5;
    const int lane = tid & 31;
    const int wm = wid & 1;        // 2 warp rows (64 M each)
    const int wn = wid >> 1;       // 2 warp cols (32 N each)

    uint32_t sb = (smem_u32(dsm) + 1023) & ~1023u;

    Loader L;
    loader_init(L, tid, m0, n0);

    // ldmatrix base offsets + swizzle masks (constant per thread)
    const uint32_t aRow = (uint32_t)(wm * 64 + (lane & 15));
    const uint32_t aRaw = aRow * 128 + (uint32_t)(lane >> 4) * 16;
    const uint32_t aMsk = (aRow & 7) << 4;
    const uint32_t bRow = (uint32_t)(wn * 32 + ((lane >> 4) << 3) + (lane & 7));
    const uint32_t bRaw = bRow * 128 + (uint32_t)((lane >> 3) & 1) * 16;
    const uint32_t bMsk = (bRow & 7) << 4;

    float acc[4][4][4];
#pragma unroll
    for (int mi = 0; mi < 4; mi++)
#pragma unroll
        for (int ni = 0; ni < 4; ni++)
#pragma unroll
            for (int j = 0; j < 4; j++) acc[mi][ni][j] = 0.f;

    const char* Ab = (const char*)A;
    const char* Bb = (const char*)B;
    load_stage(L, sb, Ab, Bb, 0);
    load_stage(L, sb, Ab, Bb, 1);

    for (int s = 0; s < GNS; s++) {
        const uint32_t ab = sb + (uint32_t)((s % NBUF) * BUF_BYTES);
        if (s < GNS - 1) asm volatile("cp.async.wait_group 1;" ::: "memory");
        else             asm volatile("cp.async.wait_group 0;" ::: "memory");
        __syncthreads();

#pragma unroll
        for (int kk = 0; kk < 4; kk++) {
            const uint32_t kb = (uint32_t)(kk * 32);  // 16 fp16 per kstep
            uint32_t ah[4][4], bh[4][2];
#pragma unroll
            for (int mi = 0; mi < 4; mi++) {
                uint32_t raw = aRaw + (uint32_t)(mi * 2048) + kb;
                ldsm4(ah[mi][0], ah[mi][1], ah[mi][2], ah[mi][3],
                      ab + (raw ^ aMsk));
            }
#pragma unroll
            for (int np = 0; np < 2; np++) {  // each x4 covers two n8 tiles
                uint32_t raw = bRaw + (uint32_t)(np * 2048) + kb;
                ldsm4(bh[np * 2][0], bh[np * 2][1], bh[np * 2 + 1][0],
                      bh[np * 2 + 1][1], ab + A_BYTES + (raw ^ bMsk));
            }
#pragma unroll
            for (int mi = 0; mi < 4; mi++)
#pragma unroll
                for (int ni = 0; ni < 4; ni++)
                    mma16816(acc[mi][ni], ah[mi], bh[ni][0], bh[ni][1]);
        }
        if (s + 2 < GNS)
            load_stage(L, sb, Ab, Bb, s + 2);
    }

    // epilogue
    const int rq = lane >> 2;
    const int cq = (lane & 3) * 2;
#pragma unroll
    for (int mi = 0; mi < 4; mi++) {
        int mrow = m0 + wm * 64 + mi * 16 + rq;
#pragma unroll
        for (int ni = 0; ni < 4; ni++) {
            long o0 = (long)mrow * CC + n0 + wn * 32 + ni * 8 + cq;
            long o1 = o0 + 8L * CC;
            float2 r0 = make_float2(acc[mi][ni][0], acc[mi][ni][1]);
            float2 r1 = make_float2(acc[mi][ni][2], acc[mi][ni][3]);
            if (mode == 1) {           // exp
                r0.x = expf(r0.x); r0.y = expf(r0.y);
                r1.x = expf(r1.x); r1.y = expf(r1.y);
            } else if (mode == 2) {    // sigmoid
                r0.x = 1.f / (1.f + expf(-r0.x));
                r0.y = 1.f / (1.f + expf(-r0.y));
                r1.x = 1.f / (1.f + expf(-r1.x));
                r1.y = 1.f / (1.f + expf(-r1.y));
            }
            *reinterpret_cast<float2*>(C + o0) = r0;
            *reinterpret_cast<float2*>(C + o1) = r1;
        }
    }
}

// fused k/v/r GEMM: grid.z selects operand set
__global__ __launch_bounds__(128, 3) void gemm3_kernel() {
    extern __shared__ char dsm[];
    int z = blockIdx.z;
    const __half* A = (z == 0) ? g_ak : (z == 1) ? g_av : g_ar;
    const __half* B = (z == 0) ? g_wk : (z == 1) ? g_wv : g_wr;
    float* C = (z == 0) ? g_k : (z == 1) ? g_v : g_r;
    int mode = (z == 0) ? 1 : (z == 1) ? 0 : 2;
    gemm_core(A, B, C, mode, blockIdx.y * GM, blockIdx.x * GN, dsm);
}

// output GEMM
__global__ __launch_bounds__(128, 3) void gemmo_kernel(float* __restrict__ C) {
    extern __shared__ char dsm[];
    gemm_core(g_a2, g_wo, C, 0, blockIdx.y * GM, blockIdx.x * GN, dsm);
}

// ---------------- chunked linear-recurrence scan ----------------
// g_k holds ek=exp(k), g_v holds v raw, g_r holds sr=sigmoid(r).
__global__ void scan1_kernel() {
    int c = blockIdx.y * blockDim.x + threadIdx.x;
    int ch = blockIdx.x;
    float w = g_ew[c];
    float P = 0.f, Q = 0.f;
    int idx = ch * CHUNK * CC + c;
#pragma unroll 8
    for (int i = 0; i < CHUNK; i++) {
        float ek = g_k[idx];
        P = fmaf(w, P, ek * g_v[idx]);
        Q = fmaf(w, Q, ek);
        idx += CC;
    }
    g_pp[ch * CC + c] = P;
    g_pq[ch * CC + c] = Q;
}

__global__ void scan2_kernel() {
    int c = blockIdx.x * blockDim.x + threadIdx.x;
    float wl = g_ewL[c];
    float P = 0.f, Q = 0.f;
#pragma unroll
    for (int j = 0; j < NCHUNK; j++) {
        g_ip[j * CC + c] = P;
        g_iq[j * CC + c] = Q;
        P = fmaf(wl, P, g_pp[j * CC + c]);
        Q = fmaf(wl, Q, g_pq[j * CC + c]);
    }
}

__global__ void scan3_kernel() {
    int c = blockIdx.y * blockDim.x + threadIdx.x;
    int ch = blockIdx.x;
    float w = g_ew[c], eu = g_eu[c];
    float P = g_ip[ch * CC + c], Q = g_iq[ch * CC + c];
    int idx = ch * CHUNK * CC + c;
#pragma unroll 4
    for (int i = 0; i < CHUNK; i++) {
        float ek = g_k[idx];
        float ekv = ek * g_v[idx];
        float num = fmaf(eu, ekv, P);
        float den = fmaf(eu, ek, Q);
        float y = g_r[idx] * __fdividef(num, den);
        g_a2[idx] = __float2half_rn(y);
        P = fmaf(w, P, ekv);
        Q = fmaf(w, Q, ek);
        idx += CC;
    }
}

// ---------------- launch ----------------
extern "C" void kernel_launch(void* const* d_in, const int* in_sizes, int n_in,
                              void* d_out, int out_size) {
    const float* x   = (const float*)d_in[0];
    const float* tf  = (const float*)d_in[1];
    const float* td  = (const float*)d_in[2];
    const float* tmk = (const float*)d_in[3];
    const float* tmv = (const float*)d_in[4];
    const float* tmr = (const float*)d_in[5];
    const float* Wk  = (const float*)d_in[6];
    const float* Wv  = (const float*)d_in[7];
    const float* Wr  = (const float*)d_in[8];
    const float* Wo  = (const float*)d_in[9];
    float* out = (float*)d_out;

    cudaFuncSetAttribute(gemm3_kernel,
                         cudaFuncAttributeMaxDynamicSharedMemorySize, SMEM_DYN);
    cudaFuncSetAttribute(gemmo_kernel,
                         cudaFuncAttributeMaxDynamicSharedMemorySize, SMEM_DYN);

    precompute_kernel<<<(CC + 255) / 256, 256>>>(tf, td);

    wsplit4_kernel<<<dim3(CC / 32, CC / 32, 4), dim3(32, 8)>>>(Wk, Wv, Wr, Wo);

    asplit_kernel<<<(TT * CC + 255) / 256, 256>>>(x, tmk, tmv, tmr);

    gemm3_kernel<<<dim3(CC / GN, TT / GM, 3), 128, SMEM_DYN>>>();

    scan1_kernel<<<dim3(NCHUNK, CC / 256), 256>>>();
    scan2_kernel<<<CC / 256, 256>>>();
    scan3_kernel<<<dim3(NCHUNK, CC / 256), 256>>>();

    gemmo_kernel<<<dim3(CC / GN, TT / GM), 128, SMEM_DYN>>>(out);
}

// round 16
// speedup vs baseline: 1.3835x; 1.0374x over previous
#include <cuda_runtime.h>
#include <cuda_fp16.h>
#include <math.h>
#include <stdint.h>

// Problem constants (T=4096, NE=DA=2048)
#define TT 4096
#define CC 2048
#define CHUNK 64
#define NCHUNK (TT / CHUNK)

// ---------------- scratch (no cudaMalloc allowed) ----------------
__device__ float g_k[TT * CC];    // exp(k)
__device__ float g_v[TT * CC];    // v (raw)
__device__ float g_r[TT * CC];    // sigmoid(r)
__device__ __half g_ak[TT * CC];
__device__ __half g_av[TT * CC];
__device__ __half g_ar[TT * CC];
__device__ __half g_a2[TT * CC];
__device__ __half g_wk[CC * CC];
__device__ __half g_wv[CC * CC];
__device__ __half g_wr[CC * CC];
__device__ __half g_wo[CC * CC];
__device__ float g_pp[NCHUNK * CC];
__device__ float g_pq[NCHUNK * CC];
__device__ float g_ip[NCHUNK * CC];
__device__ float g_iq[NCHUNK * CC];
__device__ float g_ew[CC];
__device__ float g_ewL[CC];
__device__ float g_eu[CC];

// ---------------- fused prep: weight transpose x4 + activation mix + consts ----
// grid (64, 32, 5), block 256.
//  z<4 : transpose W_z [K,N]->fp16 [N,K].  64(k) x 32(n) tile per block.
//  z==4: asplit (2048 blocks x 256 thr x 16 elems) + precompute (first 8 blocks).
__global__ __launch_bounds__(256) void prep_kernel(
    const float* __restrict__ W0, const float* __restrict__ W1,
    const float* __restrict__ W2, const float* __restrict__ W3,
    const float* __restrict__ x,
    const float* __restrict__ tmk, const float* __restrict__ tmv,
    const float* __restrict__ tmr,
    const float* __restrict__ tf, const float* __restrict__ td) {
    const int t = threadIdx.x;
    const int z = blockIdx.z;
    if (z < 4) {
        __shared__ float tile[64][33];
        const float* W = (z == 0) ? W0 : (z == 1) ? W1 : (z == 2) ? W2 : W3;
        __half* H = (z == 0) ? g_wk : (z == 1) ? g_wv : (z == 2) ? g_wr : g_wo;
        const int n0 = blockIdx.x * 32, k0 = blockIdx.y * 64;
        const int tr = t >> 5, tc = t & 31;
#pragma unroll
        for (int i = 0; i < 8; i++)   // 64 k-rows, 32 n-cols, 128B reads
            tile[tr + i * 8][tc] = W[(long)(k0 + tr + i * 8) * CC + n0 + tc];
        __syncthreads();
#pragma unroll
        for (int i = 0; i < 4; i++) { // write [n][k] as half2, 128B segments
            int nl = tr + i * 8;      // 0..31
            int kl = tc * 2;          // 0..62
            __half2 h = __floats2half2_rn(tile[kl][nl], tile[kl + 1][nl]);
            *reinterpret_cast<__half2*>(&H[(long)(n0 + nl) * CC + k0 + kl]) = h;
        }
    } else {
        const int bid = blockIdx.y * 64 + blockIdx.x;   // 0..2047
        if (bid < 8) {  // precompute per-channel constants
            int c = bid * 256 + t;
            float w = expf(-expf(td[c]));
            g_ew[c] = w;
            float p = w;
#pragma unroll
            for (int i = 0; i < 6; i++) p = p * p;      // w^64
            g_ewL[c] = p;
            g_eu[c] = expf(tf[c]);
        }
        const float4* x4 = (const float4*)x;
#pragma unroll
        for (int j = 0; j < 4; j++) {
            int i4 = bid * 1024 + j * 256 + t;          // float4 index
            int c4 = i4 & 511;                          // channel float4 index
            float4 xv = x4[i4];
            float4 xx = make_float4(0.f, 0.f, 0.f, 0.f);
            if (i4 >= 512) xx = x4[i4 - 512];
            float4 mk = ((const float4*)tmk)[c4];
            float4 mv = ((const float4*)tmv)[c4];
            float4 mr = ((const float4*)tmr)[c4];
            float dx0 = xv.x - xx.x, dx1 = xv.y - xx.y,
                  dx2 = xv.z - xx.z, dx3 = xv.w - xx.w;
            long i = (long)i4 * 4;
            __half2* pk = reinterpret_cast<__half2*>(&g_ak[i]);
            __half2* pv = reinterpret_cast<__half2*>(&g_av[i]);
            __half2* pr = reinterpret_cast<__half2*>(&g_ar[i]);
            pk[0] = __floats2half2_rn(fmaf(mk.x, dx0, xx.x), fmaf(mk.y, dx1, xx.y));
            pk[1] = __floats2half2_rn(fmaf(mk.z, dx2, xx.z), fmaf(mk.w, dx3, xx.w));
            pv[0] = __floats2half2_rn(fmaf(mv.x, dx0, xx.x), fmaf(mv.y, dx1, xx.y));
            pv[1] = __floats2half2_rn(fmaf(mv.z, dx2, xx.z), fmaf(mv.w, dx3, xx.w));
            pr[0] = __floats2half2_rn(fmaf(mr.x, dx0, xx.x), fmaf(mr.y, dx1, xx.y));
            pr[1] = __floats2half2_rn(fmaf(mr.z, dx2, xx.z), fmaf(mr.w, dx3, xx.w));
        }
    }
}

// ---------------- fp16 GEMM via mma.sync ----------------
// 128x64 CTA tile, 4 warps (warp tile 64x32), 3 CTAs/SM, NBUF=3.
#define GM 128
#define GN 64
#define GK 64
#define GNS (CC / GK)         // 32 K-stages
#define A_BYTES 16384
#define B_BYTES 8192
#define BUF_BYTES (A_BYTES + B_BYTES)   // 24576
#define NBUF 3
#define SMEM_DYN (NBUF * BUF_BYTES + 1024)

__device__ __forceinline__ uint32_t smem_u32(const void* p) {
    uint32_t a;
    asm("{ .reg .u64 t; cvta.to.shared.u64 t, %1; cvt.u32.u64 %0, t; }"
        : "=r"(a) : "l"(p));
    return a;
}
__device__ __forceinline__ void cp16(uint32_t dst, const void* src) {
    asm volatile("cp.async.cg.shared.global [%0], [%1], 16;" :: "r"(dst), "l"(src) : "memory");
}
__device__ __forceinline__ void ldsm4(uint32_t& r0, uint32_t& r1, uint32_t& r2,
                                      uint32_t& r3, uint32_t addr) {
    asm volatile("ldmatrix.sync.aligned.m8n8.x4.shared.b16 {%0,%1,%2,%3}, [%4];"
                 : "=r"(r0), "=r"(r1), "=r"(r2), "=r"(r3) : "r"(addr));
}
__device__ __forceinline__ void mma16816(float* c, const uint32_t* a,
                                         uint32_t b0, uint32_t b1) {
    asm volatile(
        "mma.sync.aligned.m16n8k16.row.col.f32.f16.f16.f32 "
        "{%0,%1,%2,%3}, {%4,%5,%6,%7}, {%8,%9}, {%0,%1,%2,%3};"
        : "+f"(c[0]), "+f"(c[1]), "+f"(c[2]), "+f"(c[3])
        : "r"(a[0]), "r"(a[1]), "r"(a[2]), "r"(a[3]), "r"(b0), "r"(b1));
}

// Per-thread stage loader with fully precomputed addresses.
struct Loader {
    uint32_t swoff[12];   // swizzled smem offset within buffer
    uint32_t goff[12];    // gmem byte offset (stage 0)
};

__device__ __forceinline__ void loader_init(Loader& L, int tid, int m0, int n0) {
    const int r0 = tid >> 3;
    const int colb = (tid & 7) * 16;
#pragma unroll
    for (int i = 0; i < 8; i++) {        // A rows r0 + 16i
        int row = r0 + i * 16;
        uint32_t off = (uint32_t)(row * 128 + colb);
        L.swoff[i] = off ^ (uint32_t)((row & 7) << 4);
        L.goff[i] = (uint32_t)((m0 + row) * (CC * 2) + colb);
    }
#pragma unroll
    for (int i = 0; i < 4; i++) {        // B rows r0 + 16i
        int row = r0 + i * 16;
        uint32_t off = (uint32_t)(A_BYTES + row * 128 + colb);
        L.swoff[8 + i] = off ^ (uint32_t)((row & 7) << 4);
        L.goff[8 + i] = (uint32_t)((n0 + row) * (CC * 2) + colb);
    }
}

__device__ __forceinline__ void load_stage(const Loader& L, uint32_t base,
                                           const char* A, const char* B,
                                           uint32_t kadd) {
#pragma unroll
    for (int i = 0; i < 8; i++)
        cp16(base + L.swoff[i], A + L.goff[i] + kadd);
#pragma unroll
    for (int i = 0; i < 4; i++)
        cp16(base + L.swoff[8 + i], B + L.goff[8 + i] + kadd);
    asm volatile("cp.async.commit_group;" ::: "memory");
}

__device__ __forceinline__ void gemm_core(
    const __half* __restrict__ A, const __half* __restrict__ B,
    float* __restrict__ C, int mode, int m0, int n0, char* dsm) {
    const int tid = threadIdx.x;
    const int wid = tid >> 5;
    const int lane = tid & 31;
    const int wm = wid & 1;
    const int wn = wid >> 1;

    uint32_t sb = (smem_u32(dsm) + 1023) & ~1023u;
    const uint32_t send = sb + NBUF * BUF_BYTES;

    Loader L;
    loader_init(L, tid, m0, n0);

    const uint32_t aRow = (uint32_t)(wm * 64 + (lane & 15));
    const uint32_t aRaw = aRow * 128 + (uint32_t)(lane >> 4) * 16;
    const uint32_t aMsk = (aRow & 7) << 4;
    const uint32_t bRow = (uint32_t)(wn * 32 + ((lane >> 4) << 3) + (lane & 7));
    const uint32_t bRaw = bRow * 128 + (uint32_t)((lane >> 3) & 1) * 16;
    const uint32_t bMsk = (bRow & 7) << 4;

    float acc[4][4][4];
#pragma unroll
    for (int mi = 0; mi < 4; mi++)
#pragma unroll
        for (int ni = 0; ni < 4; ni++)
#pragma unroll
            for (int j = 0; j < 4; j++) acc[mi][ni][j] = 0.f;

    const char* Ab = (const char*)A;
    const char* Bb = (const char*)B;
    load_stage(L, sb, Ab, Bb, 0);
    load_stage(L, sb + BUF_BYTES, Ab, Bb, 128);

    uint32_t cbuf = sb;                      // compute buffer (stage s)
    uint32_t lbuf = sb + 2u * BUF_BYTES;     // load target (stage s+2)
    uint32_t lkadd = 256;                    // 128B per stage

    for (int s = 0; s < GNS; s++) {
        if (s < GNS - 1) asm volatile("cp.async.wait_group 1;" ::: "memory");
        else             asm volatile("cp.async.wait_group 0;" ::: "memory");
        __syncthreads();

#pragma unroll
        for (int kk = 0; kk < 4; kk++) {
            const uint32_t kb = (uint32_t)(kk * 32);
            uint32_t ah[4][4], bh[4][2];
#pragma unroll
            for (int mi = 0; mi < 4; mi++) {
                uint32_t raw = aRaw + (uint32_t)(mi * 2048) + kb;
                ldsm4(ah[mi][0], ah[mi][1], ah[mi][2], ah[mi][3],
                      cbuf + (raw ^ aMsk));
            }
#pragma unroll
            for (int np = 0; np < 2; np++) {
                uint32_t raw = bRaw + (uint32_t)(np * 2048) + kb;
                ldsm4(bh[np * 2][0], bh[np * 2][1], bh[np * 2 + 1][0],
                      bh[np * 2 + 1][1], cbuf + A_BYTES + (raw ^ bMsk));
            }
#pragma unroll
            for (int mi = 0; mi < 4; mi++)
#pragma unroll
                for (int ni = 0; ni < 4; ni++)
                    mma16816(acc[mi][ni], ah[mi], bh[ni][0], bh[ni][1]);
        }
        if (s + 2 < GNS) {
            load_stage(L, lbuf, Ab, Bb, lkadd);
            lkadd += 128;
        }
        cbuf += BUF_BYTES; if (cbuf == send) cbuf = sb;
        lbuf += BUF_BYTES; if (lbuf == send) lbuf = sb;
    }

    const int rq = lane >> 2;
    const int cq = (lane & 3) * 2;
#pragma unroll
    for (int mi = 0; mi < 4; mi++) {
        int mrow = m0 + wm * 64 + mi * 16 + rq;
#pragma unroll
        for (int ni = 0; ni < 4; ni++) {
            long o0 = (long)mrow * CC + n0 + wn * 32 + ni * 8 + cq;
            long o1 = o0 + 8L * CC;
            float2 r0 = make_float2(acc[mi][ni][0], acc[mi][ni][1]);
            float2 r1 = make_float2(acc[mi][ni][2], acc[mi][ni][3]);
            if (mode == 1) {
                r0.x = expf(r0.x); r0.y = expf(r0.y);
                r1.x = expf(r1.x); r1.y = expf(r1.y);
            } else if (mode == 2) {
                r0.x = 1.f / (1.f + expf(-r0.x));
                r0.y = 1.f / (1.f + expf(-r0.y));
                r1.x = 1.f / (1.f + expf(-r1.x));
                r1.y = 1.f / (1.f + expf(-r1.y));
            }
            *reinterpret_cast<float2*>(C + o0) = r0;
            *reinterpret_cast<float2*>(C + o1) = r1;
        }
    }
}

__global__ __launch_bounds__(128, 3) void gemm3_kernel() {
    extern __shared__ char dsm[];
    int z = blockIdx.z;
    const __half* A = (z == 0) ? g_ak : (z == 1) ? g_av : g_ar;
    const __half* B = (z == 0) ? g_wk : (z == 1) ? g_wv : g_wr;
    float* C = (z == 0) ? g_k : (z == 1) ? g_v : g_r;
    int mode = (z == 0) ? 1 : (z == 1) ? 0 : 2;
    gemm_core(A, B, C, mode, blockIdx.y * GM, blockIdx.x * GN, dsm);
}

__global__ __launch_bounds__(128, 3) void gemmo_kernel(float* __restrict__ C) {
    extern __shared__ char dsm[];
    gemm_core(g_a2, g_wo, C, 0, blockIdx.y * GM, blockIdx.x * GN, dsm);
}

// ---------------- chunked linear-recurrence scan (2 channels/thread) -------
__global__ void scan1_kernel() {
    int c = 2 * (blockIdx.y * blockDim.x + threadIdx.x);
    int ch = blockIdx.x;
    float2 w = *reinterpret_cast<const float2*>(&g_ew[c]);
    float2 P = make_float2(0.f, 0.f), Q = make_float2(0.f, 0.f);
    int idx = ch * CHUNK * CC + c;
#pragma unroll 8
    for (int i = 0; i < CHUNK; i++) {
        float2 ek = *reinterpret_cast<const float2*>(&g_k[idx]);
        float2 vv = *reinterpret_cast<const float2*>(&g_v[idx]);
        P.x = fmaf(w.x, P.x, ek.x * vv.x);
        P.y = fmaf(w.y, P.y, ek.y * vv.y);
        Q.x = fmaf(w.x, Q.x, ek.x);
        Q.y = fmaf(w.y, Q.y, ek.y);
        idx += CC;
    }
    *reinterpret_cast<float2*>(&g_pp[ch * CC + c]) = P;
    *reinterpret_cast<float2*>(&g_pq[ch * CC + c]) = Q;
}

__global__ void scan2_kernel() {
    int c = 2 * (blockIdx.x * blockDim.x + threadIdx.x);
    float2 wl = *reinterpret_cast<const float2*>(&g_ewL[c]);
    float2 P = make_float2(0.f, 0.f), Q = make_float2(0.f, 0.f);
#pragma unroll
    for (int j = 0; j < NCHUNK; j++) {
        *reinterpret_cast<float2*>(&g_ip[j * CC + c]) = P;
        *reinterpret_cast<float2*>(&g_iq[j * CC + c]) = Q;
        float2 pp = *reinterpret_cast<const float2*>(&g_pp[j * CC + c]);
        float2 pq = *reinterpret_cast<const float2*>(&g_pq[j * CC + c]);
        P.x = fmaf(wl.x, P.x, pp.x);
        P.y = fmaf(wl.y, P.y, pp.y);
        Q.x = fmaf(wl.x, Q.x, pq.x);
        Q.y = fmaf(wl.y, Q.y, pq.y);
    }
}

__global__ void scan3_kernel() {
    int c = 2 * (blockIdx.y * blockDim.x + threadIdx.x);
    int ch = blockIdx.x;
    float2 w = *reinterpret_cast<const float2*>(&g_ew[c]);
    float2 eu = *reinterpret_cast<const float2*>(&g_eu[c]);
    float2 P = *reinterpret_cast<const float2*>(&g_ip[ch * CC + c]);
    float2 Q = *reinterpret_cast<const float2*>(&g_iq[ch * CC + c]);
    int idx = ch * CHUNK * CC + c;
#pragma unroll 4
    for (int i = 0; i < CHUNK; i++) {
        float2 ek = *reinterpret_cast<const float2*>(&g_k[idx]);
        float2 vv = *reinterpret_cast<const float2*>(&g_v[idx]);
        float2 sr = *reinterpret_cast<const float2*>(&g_r[idx]);
        float ekv0 = ek.x * vv.x, ekv1 = ek.y * vv.y;
        float y0 = sr.x * __fdividef(fmaf(eu.x, ekv0, P.x), fmaf(eu.x, ek.x, Q.x));
        float y1 = sr.y * __fdividef(fmaf(eu.y, ekv1, P.y), fmaf(eu.y, ek.y, Q.y));
        *reinterpret_cast<__half2*>(&g_a2[idx]) = __floats2half2_rn(y0, y1);
        P.x = fmaf(w.x, P.x, ekv0);
        P.y = fmaf(w.y, P.y, ekv1);
        Q.x = fmaf(w.x, Q.x, ek.x);
        Q.y = fmaf(w.y, Q.y, ek.y);
        idx += CC;
    }
}

// ---------------- launch ----------------
extern "C" void kernel_launch(void* const* d_in, const int* in_sizes, int n_in,
                              void* d_out, int out_size) {
    const float* x   = (const float*)d_in[0];
    const float* tf  = (const float*)d_in[1];
    const float* td  = (const float*)d_in[2];
    const float* tmk = (const float*)d_in[3];
    const float* tmv = (const float*)d_in[4];
    const float* tmr = (const float*)d_in[5];
    const float* Wk  = (const float*)d_in[6];
    const float* Wv  = (const float*)d_in[7];
    const float* Wr  = (const float*)d_in[8];
    const float* Wo  = (const float*)d_in[9];
    float* out = (float*)d_out;

    cudaFuncSetAttribute(gemm3_kernel,
                         cudaFuncAttributeMaxDynamicSharedMemorySize, SMEM_DYN);
    cudaFuncSetAttribute(gemmo_kernel,
                         cudaFuncAttributeMaxDynamicSharedMemorySize, SMEM_DYN);

    prep_kernel<<<dim3(64, 32, 5), 256>>>(Wk, Wv, Wr, Wo, x, tmk, tmv, tmr, tf, td);

    gemm3_kernel<<<dim3(CC / GN, TT / GM, 3), 128, SMEM_DYN>>>();

    scan1_kernel<<<dim3(NCHUNK, CC / 512), 256>>>();
    scan2_kernel<<<CC / 512, 256>>>();
    scan3_kernel<<<dim3(NCHUNK, CC / 512), 256>>>();

    gemmo_kernel<<<dim3(CC / GN, TT / GM), 128, SMEM_DYN>>>(out);
}

// round 17
// speedup vs baseline: 1.4491x; 1.0474x over previous
#include <cuda_runtime.h>
#include <cuda_fp16.h>
#include <math.h>
#include <stdint.h>

// Problem constants (T=4096, NE=DA=2048)
#define TT 4096
#define CC 2048
#define CHUNK 64
#define NCHUNK (TT / CHUNK)

// ---------------- scratch (no cudaMalloc allowed) ----------------
__device__ float g_k[TT * CC];    // exp(k)
__device__ float g_v[TT * CC];    // v (raw)
__device__ float g_r[TT * CC];    // sigmoid(r)
__device__ __half g_ak[TT * CC];
__device__ __half g_av[TT * CC];
__device__ __half g_ar[TT * CC];
__device__ __half g_a2[TT * CC];
__device__ __half g_wk[CC * CC];
__device__ __half g_wv[CC * CC];
__device__ __half g_wr[CC * CC];
__device__ __half g_wo[CC * CC];
__device__ float g_pp[NCHUNK * CC];
__device__ float g_pq[NCHUNK * CC];
__device__ float g_ip[NCHUNK * CC];
__device__ float g_iq[NCHUNK * CC];
__device__ float g_ew[CC];
__device__ float g_ewL[CC];
__device__ float g_eu[CC];

// ---------------- fused prep: weight transpose x4 + activation mix + consts ----
__global__ __launch_bounds__(256) void prep_kernel(
    const float* __restrict__ W0, const float* __restrict__ W1,
    const float* __restrict__ W2, const float* __restrict__ W3,
    const float* __restrict__ x,
    const float* __restrict__ tmk, const float* __restrict__ tmv,
    const float* __restrict__ tmr,
    const float* __restrict__ tf, const float* __restrict__ td) {
    const int t = threadIdx.x;
    const int z = blockIdx.z;
    if (z < 4) {
        __shared__ float tile[64][33];
        const float* W = (z == 0) ? W0 : (z == 1) ? W1 : (z == 2) ? W2 : W3;
        __half* H = (z == 0) ? g_wk : (z == 1) ? g_wv : (z == 2) ? g_wr : g_wo;
        const int n0 = blockIdx.x * 32, k0 = blockIdx.y * 64;
        const int tr = t >> 5, tc = t & 31;
#pragma unroll
        for (int i = 0; i < 8; i++)
            tile[tr + i * 8][tc] = W[(long)(k0 + tr + i * 8) * CC + n0 + tc];
        __syncthreads();
#pragma unroll
        for (int i = 0; i < 4; i++) {
            int nl = tr + i * 8;
            int kl = tc * 2;
            __half2 h = __floats2half2_rn(tile[kl][nl], tile[kl + 1][nl]);
            *reinterpret_cast<__half2*>(&H[(long)(n0 + nl) * CC + k0 + kl]) = h;
        }
    } else {
        const int bid = blockIdx.y * 64 + blockIdx.x;   // 0..2047
        if (bid < 8) {
            int c = bid * 256 + t;
            float w = expf(-expf(td[c]));
            g_ew[c] = w;
            float p = w;
#pragma unroll
            for (int i = 0; i < 6; i++) p = p * p;      // w^64
            g_ewL[c] = p;
            g_eu[c] = expf(tf[c]);
        }
        const float4* x4 = (const float4*)x;
#pragma unroll
        for (int j = 0; j < 4; j++) {
            int i4 = bid * 1024 + j * 256 + t;
            int c4 = i4 & 511;
            float4 xv = x4[i4];
            float4 xx = make_float4(0.f, 0.f, 0.f, 0.f);
            if (i4 >= 512) xx = x4[i4 - 512];
            float4 mk = ((const float4*)tmk)[c4];
            float4 mv = ((const float4*)tmv)[c4];
            float4 mr = ((const float4*)tmr)[c4];
            float dx0 = xv.x - xx.x, dx1 = xv.y - xx.y,
                  dx2 = xv.z - xx.z, dx3 = xv.w - xx.w;
            long i = (long)i4 * 4;
            __half2* pk = reinterpret_cast<__half2*>(&g_ak[i]);
            __half2* pv = reinterpret_cast<__half2*>(&g_av[i]);
            __half2* pr = reinterpret_cast<__half2*>(&g_ar[i]);
            pk[0] = __floats2half2_rn(fmaf(mk.x, dx0, xx.x), fmaf(mk.y, dx1, xx.y));
            pk[1] = __floats2half2_rn(fmaf(mk.z, dx2, xx.z), fmaf(mk.w, dx3, xx.w));
            pv[0] = __floats2half2_rn(fmaf(mv.x, dx0, xx.x), fmaf(mv.y, dx1, xx.y));
            pv[1] = __floats2half2_rn(fmaf(mv.z, dx2, xx.z), fmaf(mv.w, dx3, xx.w));
            pr[0] = __floats2half2_rn(fmaf(mr.x, dx0, xx.x), fmaf(mr.y, dx1, xx.y));
            pr[1] = __floats2half2_rn(fmaf(mr.z, dx2, xx.z), fmaf(mr.w, dx3, xx.w));
        }
    }
}

// ---------------- fp16 GEMM via mma.sync ----------------
#define GM 128
#define GN 64
#define GK 64
#define GNS (CC / GK)
#define A_BYTES 16384
#define B_BYTES 8192
#define BUF_BYTES (A_BYTES + B_BYTES)
#define NBUF 3
#define SMEM_DYN (NBUF * BUF_BYTES + 1024)

__device__ __forceinline__ uint32_t smem_u32(const void* p) {
    uint32_t a;
    asm("{ .reg .u64 t; cvta.to.shared.u64 t, %1; cvt.u32.u64 %0, t; }"
        : "=r"(a) : "l"(p));
    return a;
}
__device__ __forceinline__ void cp16(uint32_t dst, const void* src) {
    asm volatile("cp.async.cg.shared.global [%0], [%1], 16;" :: "r"(dst), "l"(src) : "memory");
}
__device__ __forceinline__ void ldsm4(uint32_t& r0, uint32_t& r1, uint32_t& r2,
                                      uint32_t& r3, uint32_t addr) {
    asm volatile("ldmatrix.sync.aligned.m8n8.x4.shared.b16 {%0,%1,%2,%3}, [%4];"
                 : "=r"(r0), "=r"(r1), "=r"(r2), "=r"(r3) : "r"(addr));
}
__device__ __forceinline__ void mma16816(float* c, const uint32_t* a,
                                         uint32_t b0, uint32_t b1) {
    asm volatile(
        "mma.sync.aligned.m16n8k16.row.col.f32.f16.f16.f32 "
        "{%0,%1,%2,%3}, {%4,%5,%6,%7}, {%8,%9}, {%0,%1,%2,%3};"
        : "+f"(c[0]), "+f"(c[1]), "+f"(c[2]), "+f"(c[3])
        : "r"(a[0]), "r"(a[1]), "r"(a[2]), "r"(a[3]), "r"(b0), "r"(b1));
}

struct Loader {
    uint32_t swoff[12];
    uint32_t goff[12];
};

__device__ __forceinline__ void loader_init(Loader& L, int tid, int m0, int n0) {
    const int r0 = tid >> 3;
    const int colb = (tid & 7) * 16;
#pragma unroll
    for (int i = 0; i < 8; i++) {
        int row = r0 + i * 16;
        uint32_t off = (uint32_t)(row * 128 + colb);
        L.swoff[i] = off ^ (uint32_t)((row & 7) << 4);
        L.goff[i] = (uint32_t)((m0 + row) * (CC * 2) + colb);
    }
#pragma unroll
    for (int i = 0; i < 4; i++) {
        int row = r0 + i * 16;
        uint32_t off = (uint32_t)(A_BYTES + row * 128 + colb);
        L.swoff[8 + i] = off ^ (uint32_t)((row & 7) << 4);
        L.goff[8 + i] = (uint32_t)((n0 + row) * (CC * 2) + colb);
    }
}

__device__ __forceinline__ void load_stage(const Loader& L, uint32_t base,
                                           const char* A, const char* B,
                                           uint32_t kadd) {
#pragma unroll
    for (int i = 0; i < 8; i++)
        cp16(base + L.swoff[i], A + L.goff[i] + kadd);
#pragma unroll
    for (int i = 0; i < 4; i++)
        cp16(base + L.swoff[8 + i], B + L.goff[8 + i] + kadd);
    asm volatile("cp.async.commit_group;" ::: "memory");
}

__device__ __forceinline__ void gemm_core(
    const __half* __restrict__ A, const __half* __restrict__ B,
    float* __restrict__ C, int mode, int m0, int n0, char* dsm) {
    const int tid = threadIdx.x;
    const int wid = tid >> 5;
    const int lane = tid & 31;
    const int wm = wid & 1;
    const int wn = wid >> 1;

    uint32_t sb = (smem_u32(dsm) + 1023) & ~1023u;
    const uint32_t send = sb + NBUF * BUF_BYTES;

    Loader L;
    loader_init(L, tid, m0, n0);

    const uint32_t aRow = (uint32_t)(wm * 64 + (lane & 15));
    const uint32_t aRaw = aRow * 128 + (uint32_t)(lane >> 4) * 16;
    const uint32_t aMsk = (aRow & 7) << 4;
    const uint32_t bRow = (uint32_t)(wn * 32 + ((lane >> 4) << 3) + (lane & 7));
    const uint32_t bRaw = bRow * 128 + (uint32_t)((lane >> 3) & 1) * 16;
    const uint32_t bMsk = (bRow & 7) << 4;

    float acc[4][4][4];
#pragma unroll
    for (int mi = 0; mi < 4; mi++)
#pragma unroll
        for (int ni = 0; ni < 4; ni++)
#pragma unroll
            for (int j = 0; j < 4; j++) acc[mi][ni][j] = 0.f;

    const char* Ab = (const char*)A;
    const char* Bb = (const char*)B;
    load_stage(L, sb, Ab, Bb, 0);
    load_stage(L, sb + BUF_BYTES, Ab, Bb, 128);

    uint32_t cbuf = sb;
    uint32_t lbuf = sb + 2u * BUF_BYTES;
    uint32_t lkadd = 256;

    for (int s = 0; s < GNS; s++) {
        if (s < GNS - 1) asm volatile("cp.async.wait_group 1;" ::: "memory");
        else             asm volatile("cp.async.wait_group 0;" ::: "memory");
        __syncthreads();

#pragma unroll
        for (int kk = 0; kk < 4; kk++) {
            const uint32_t kb = (uint32_t)(kk * 32);
            uint32_t ah[4][4], bh[4][2];
#pragma unroll
            for (int mi = 0; mi < 4; mi++) {
                uint32_t raw = aRaw + (uint32_t)(mi * 2048) + kb;
                ldsm4(ah[mi][0], ah[mi][1], ah[mi][2], ah[mi][3],
                      cbuf + (raw ^ aMsk));
            }
#pragma unroll
            for (int np = 0; np < 2; np++) {
                uint32_t raw = bRaw + (uint32_t)(np * 2048) + kb;
                ldsm4(bh[np * 2][0], bh[np * 2][1], bh[np * 2 + 1][0],
                      bh[np * 2 + 1][1], cbuf + A_BYTES + (raw ^ bMsk));
            }
#pragma unroll
            for (int mi = 0; mi < 4; mi++)
#pragma unroll
                for (int ni = 0; ni < 4; ni++)
                    mma16816(acc[mi][ni], ah[mi], bh[ni][0], bh[ni][1]);
        }
        if (s + 2 < GNS) {
            load_stage(L, lbuf, Ab, Bb, lkadd);
            lkadd += 128;
        }
        cbuf += BUF_BYTES; if (cbuf == send) cbuf = sb;
        lbuf += BUF_BYTES; if (lbuf == send) lbuf = sb;
    }

    const int rq = lane >> 2;
    const int cq = (lane & 3) * 2;
#pragma unroll
    for (int mi = 0; mi < 4; mi++) {
        int mrow = m0 + wm * 64 + mi * 16 + rq;
#pragma unroll
        for (int ni = 0; ni < 4; ni++) {
            long o0 = (long)mrow * CC + n0 + wn * 32 + ni * 8 + cq;
            long o1 = o0 + 8L * CC;
            float2 r0 = make_float2(acc[mi][ni][0], acc[mi][ni][1]);
            float2 r1 = make_float2(acc[mi][ni][2], acc[mi][ni][3]);
            if (mode == 1) {
                r0.x = expf(r0.x); r0.y = expf(r0.y);
                r1.x = expf(r1.x); r1.y = expf(r1.y);
            } else if (mode == 2) {
                r0.x = 1.f / (1.f + expf(-r0.x));
                r0.y = 1.f / (1.f + expf(-r0.y));
                r1.x = 1.f / (1.f + expf(-r1.x));
                r1.y = 1.f / (1.f + expf(-r1.y));
            }
            *reinterpret_cast<float2*>(C + o0) = r0;
            *reinterpret_cast<float2*>(C + o1) = r1;
        }
    }
}

__global__ __launch_bounds__(128, 3) void gemm3_kernel() {
    extern __shared__ char dsm[];
    int z = blockIdx.z;
    const __half* A = (z == 0) ? g_ak : (z == 1) ? g_av : g_ar;
    const __half* B = (z == 0) ? g_wk : (z == 1) ? g_wv : g_wr;
    float* C = (z == 0) ? g_k : (z == 1) ? g_v : g_r;
    int mode = (z == 0) ? 1 : (z == 1) ? 0 : 2;
    gemm_core(A, B, C, mode, blockIdx.y * GM, blockIdx.x * GN, dsm);
}

__global__ __launch_bounds__(128, 3) void gemmo_kernel(float* __restrict__ C) {
    extern __shared__ char dsm[];
    gemm_core(g_a2, g_wo, C, 0, blockIdx.y * GM, blockIdx.x * GN, dsm);
}

// ---------------- chunked linear-recurrence scan -------
__global__ void scan1_kernel() {
    int c = 2 * (blockIdx.y * blockDim.x + threadIdx.x);
    int ch = blockIdx.x;
    float2 w = *reinterpret_cast<const float2*>(&g_ew[c]);
    float2 P = make_float2(0.f, 0.f), Q = make_float2(0.f, 0.f);
    int idx = ch * CHUNK * CC + c;
#pragma unroll 8
    for (int i = 0; i < CHUNK; i++) {
        float2 ek = *reinterpret_cast<const float2*>(&g_k[idx]);
        float2 vv = *reinterpret_cast<const float2*>(&g_v[idx]);
        P.x = fmaf(w.x, P.x, ek.x * vv.x);
        P.y = fmaf(w.y, P.y, ek.y * vv.y);
        Q.x = fmaf(w.x, Q.x, ek.x);
        Q.y = fmaf(w.y, Q.y, ek.y);
        idx += CC;
    }
    *reinterpret_cast<float2*>(&g_pp[ch * CC + c]) = P;
    *reinterpret_cast<float2*>(&g_pq[ch * CC + c]) = Q;
}

// Tree-parallel inter-chunk scan: block = 4 channels x 64 chunks.
// Inclusive weighted prefix T_j = wl*T_{j-1} + pp_j via Hillis-Steele
// (constant per-channel ratio wl => distance-additive weights), then
// exclusive output ip_j = T_{j-1}.
__global__ __launch_bounds__(256) void scan2_kernel() {
    __shared__ float Tp[NCHUNK][4];
    __shared__ float Tq[NCHUNK][4];
    const int cl = threadIdx.x & 3;
    const int j = threadIdx.x >> 2;        // chunk 0..63
    const int c = blockIdx.x * 4 + cl;
    const float wl = g_ewL[c];
    float p = g_pp[j * CC + c];
    float q = g_pq[j * CC + c];
    Tp[j][cl] = p;
    Tq[j][cl] = q;
    float f = wl;
#pragma unroll
    for (int s = 1; s <= 32; s <<= 1) {
        __syncthreads();
        float ap = 0.f, aq = 0.f;
        if (j >= s) { ap = Tp[j - s][cl]; aq = Tq[j - s][cl]; }
        __syncthreads();
        p = fmaf(f, ap, p);
        q = fmaf(f, aq, q);
        Tp[j][cl] = p;
        Tq[j][cl] = q;
        f = f * f;
    }
    __syncthreads();
    float ip = 0.f, iq = 0.f;
    if (j > 0) { ip = Tp[j - 1][cl]; iq = Tq[j - 1][cl]; }
    g_ip[j * CC + c] = ip;
    g_iq[j * CC + c] = iq;
}

__global__ void scan3_kernel() {
    int c = 2 * (blockIdx.y * blockDim.x + threadIdx.x);
    int ch = blockIdx.x;
    float2 w = *reinterpret_cast<const float2*>(&g_ew[c]);
    float2 eu = *reinterpret_cast<const float2*>(&g_eu[c]);
    float2 P = *reinterpret_cast<const float2*>(&g_ip[ch * CC + c]);
    float2 Q = *reinterpret_cast<const float2*>(&g_iq[ch * CC + c]);
    int idx = ch * CHUNK * CC + c;
#pragma unroll 4
    for (int i = 0; i < CHUNK; i++) {
        float2 ek = *reinterpret_cast<const float2*>(&g_k[idx]);
        float2 vv = *reinterpret_cast<const float2*>(&g_v[idx]);
        float2 sr = *reinterpret_cast<const float2*>(&g_r[idx]);
        float ekv0 = ek.x * vv.x, ekv1 = ek.y * vv.y;
        float y0 = sr.x * __fdividef(fmaf(eu.x, ekv0, P.x), fmaf(eu.x, ek.x, Q.x));
        float y1 = sr.y * __fdividef(fmaf(eu.y, ekv1, P.y), fmaf(eu.y, ek.y, Q.y));
        *reinterpret_cast<__half2*>(&g_a2[idx]) = __floats2half2_rn(y0, y1);
        P.x = fmaf(w.x, P.x, ekv0);
        P.y = fmaf(w.y, P.y, ekv1);
        Q.x = fmaf(w.x, Q.x, ek.x);
        Q.y = fmaf(w.y, Q.y, ek.y);
        idx += CC;
    }
}

// ---------------- launch ----------------
extern "C" void kernel_launch(void* const* d_in, const int* in_sizes, int n_in,
                              void* d_out, int out_size) {
    const float* x   = (const float*)d_in[0];
    const float* tf  = (const float*)d_in[1];
    const float* td  = (const float*)d_in[2];
    const float* tmk = (const float*)d_in[3];
    const float* tmv = (const float*)d_in[4];
    const float* tmr = (const float*)d_in[5];
    const float* Wk  = (const float*)d_in[6];
    const float* Wv  = (const float*)d_in[7];
    const float* Wr  = (const float*)d_in[8];
    const float* Wo  = (const float*)d_in[9];
    float* out = (float*)d_out;

    cudaFuncSetAttribute(gemm3_kernel,
                         cudaFuncAttributeMaxDynamicSharedMemorySize, SMEM_DYN);
    cudaFuncSetAttribute(gemmo_kernel,
                         cudaFuncAttributeMaxDynamicSharedMemorySize, SMEM_DYN);

    prep_kernel<<<dim3(64, 32, 5), 256>>>(Wk, Wv, Wr, Wo, x, tmk, tmv, tmr, tf, td);

    gemm3_kernel<<<dim3(CC / GN, TT / GM, 3), 128, SMEM_DYN>>>();

    scan1_kernel<<<dim3(NCHUNK, CC / 512), 256>>>();
    scan2_kernel<<<CC / 4, 256>>>();
    scan3_kernel<<<dim3(NCHUNK, CC / 512), 256>>>();

    gemmo_kernel<<<dim3(CC / GN, TT / GM), 128, SMEM_DYN>>>(out);
}